// round 6
// baseline (speedup 1.0000x reference)
#include <cuda_runtime.h>
#include <math.h>
#include <stdint.h>

#define TT 512
#define BB 64
#define DD 512
#define HH 512
#define GG 2048
#define KTOT 1024

typedef unsigned long long u64;

// ---------------- device scratch ----------------
__device__ float g_W[(size_t)GG * KTOT];        // 8 MB normalized weights
__device__ float g_zx[(size_t)TT * GG * BB];    // 256 MB x-projection (+bias)
__device__ float g_h[2][(size_t)HH * BB];       // h double buffer, [col][b]
__device__ unsigned g_bar_cnt;
__device__ unsigned g_bar_gen;

// ---------------- f32x2 helpers ----------------
__device__ __forceinline__ u64 pack2(float x, float y) {
    u64 r; asm("mov.b64 %0, {%1, %2};" : "=l"(r) : "f"(x), "f"(y)); return r;
}
__device__ __forceinline__ void fma2(u64& d, u64 a, u64 b) {
    asm("fma.rn.f32x2 %0, %1, %2, %0;" : "+l"(d) : "l"(a), "l"(b));
}
__device__ __forceinline__ float2 unpack2(u64 v) {
    float2 f; asm("mov.b64 {%0, %1}, %2;" : "=f"(f.x), "=f"(f.y) : "l"(v)); return f;
}

// ---------------- cp.async (L2-only) ----------------
__device__ __forceinline__ void cp_async16(void* smem_dst, const void* gsrc) {
    unsigned s = (unsigned)__cvta_generic_to_shared(smem_dst);
    asm volatile("cp.async.cg.shared.global [%0], [%1], 16;" :: "r"(s), "l"(gsrc));
}
#define CP_COMMIT() asm volatile("cp.async.commit_group;" ::: "memory")
#define CP_WAIT(n)  asm volatile("cp.async.wait_group %0;" :: "n"(n) : "memory")

__device__ __forceinline__ unsigned ld_acq(unsigned* p) {
    unsigned v;
    asm volatile("ld.acquire.gpu.u32 %0, [%1];" : "=r"(v) : "l"(p) : "memory");
    return v;
}

__device__ __forceinline__ void grid_barrier(int nblocks) {
    __syncthreads();
    if (threadIdx.x == 0) {
        unsigned gen = ld_acq(&g_bar_gen);
        __threadfence();
        unsigned arrived = atomicAdd(&g_bar_cnt, 1u);
        if (arrived == (unsigned)(nblocks - 1)) {
            atomicExch(&g_bar_cnt, 0u);
            __threadfence();
            atomicAdd(&g_bar_gen, 1u);
        } else {
            while (ld_acq(&g_bar_gen) == gen) { __nanosleep(16); }
        }
        __threadfence();
    }
    __syncthreads();
}

__device__ __forceinline__ float sigf(float x) { return 1.0f / (1.0f + expf(-x)); }

// ============================================================================
// Phase 1: weight norm
// ============================================================================
__global__ __launch_bounds__(256) void qlstm_wnorm(const float* __restrict__ v,
                                                   const float* __restrict__ g) {
    int r = blockIdx.x;
    const float* vr = v + (size_t)r * KTOT;
    float s = 0.0f;
    for (int k = threadIdx.x; k < KTOT; k += 256) { float x = vr[k]; s += x * x; }
    __shared__ float red[256];
    red[threadIdx.x] = s;
    __syncthreads();
    for (int off = 128; off > 0; off >>= 1) {
        if (threadIdx.x < off) red[threadIdx.x] += red[threadIdx.x + off];
        __syncthreads();
    }
    float scale = g[r] * rsqrtf(red[0]);
    for (int k = threadIdx.x; k < KTOT; k += 256)
        g_W[(size_t)r * KTOT + k] = vr[k] * scale;
}

// ============================================================================
// Phase 2: zx = X @ Wx^T + bias.  CTA 128r x 128n (2 timesteps), 256 thr,
// thread tile 8r x 8n, A transposed non-dup in smem, reg packs, f32x2 on n.
// ============================================================================
#define AST_PAD 132
#define BSS_PAD 132

__global__ __launch_bounds__(256) void qlstm_gemm_x(const float* __restrict__ X,
                                                    const float* __restrict__ bias) {
    __shared__ float Ast[16 * AST_PAD];   // [k][r] transposed
    __shared__ float Bs[16 * BSS_PAD];    // [k][n]

    const int rt  = blockIdx.x * 128;
    const int nt  = blockIdx.y * 128;
    const int tid = threadIdx.x;
    const int rg  = tid >> 4;
    const int ng  = tid & 15;
    const int r0  = rg * 8;
    const int n0  = ng * 8;

    u64 acc[8][4];
    #pragma unroll
    for (int i = 0; i < 8; i++)
        #pragma unroll
        for (int j = 0; j < 4; j++) acc[i][j] = 0ULL;

    for (int kt = 0; kt < DD; kt += 16) {
        __syncthreads();
        #pragma unroll
        for (int u = 0; u < 2; u++) {
            int idx = tid + u * 256;
            int r = idx >> 2, kq = (idx & 3) << 2;
            float4 va = *(const float4*)(g_W + (size_t)(rt + r) * KTOT + kt + kq);
            Ast[(kq + 0) * AST_PAD + r] = va.x;
            Ast[(kq + 1) * AST_PAD + r] = va.y;
            Ast[(kq + 2) * AST_PAD + r] = va.z;
            Ast[(kq + 3) * AST_PAD + r] = va.w;
        }
        #pragma unroll
        for (int u = 0; u < 2; u++) {
            int idx = tid + u * 256;
            int n = idx >> 2, kq = (idx & 3) << 2;
            float4 vb = *(const float4*)(X + (size_t)(nt + n) * DD + kt + kq);
            Bs[(kq + 0) * BSS_PAD + n] = vb.x;
            Bs[(kq + 1) * BSS_PAD + n] = vb.y;
            Bs[(kq + 2) * BSS_PAD + n] = vb.z;
            Bs[(kq + 3) * BSS_PAD + n] = vb.w;
        }
        __syncthreads();

        #pragma unroll
        for (int kk = 0; kk < 16; kk++) {
            ulonglong2 b01 = *(const ulonglong2*)&Bs[kk * BSS_PAD + n0];
            ulonglong2 b23 = *(const ulonglong2*)&Bs[kk * BSS_PAD + n0 + 4];
            float4 w0 = *(const float4*)&Ast[kk * AST_PAD + r0];
            float4 w1 = *(const float4*)&Ast[kk * AST_PAD + r0 + 4];
            float wv[8] = {w0.x, w0.y, w0.z, w0.w, w1.x, w1.y, w1.z, w1.w};
            #pragma unroll
            for (int i = 0; i < 8; i++) {
                u64 wd = pack2(wv[i], wv[i]);
                fma2(acc[i][0], wd, b01.x); fma2(acc[i][1], wd, b01.y);
                fma2(acc[i][2], wd, b23.x); fma2(acc[i][3], wd, b23.y);
            }
        }
    }

    const int t  = blockIdx.y * 2 + (n0 >> 6);
    const int b0 = n0 & 63;
    #pragma unroll
    for (int i = 0; i < 8; i++) {
        int r = rt + r0 + i;
        float bi = bias[r];
        float2 p0 = unpack2(acc[i][0]);
        float2 p1 = unpack2(acc[i][1]);
        float2 p2 = unpack2(acc[i][2]);
        float2 p3 = unpack2(acc[i][3]);
        float* dst = g_zx + ((size_t)t * GG + r) * BB + b0;
        *(float4*)dst       = make_float4(p0.x + bi, p0.y + bi, p1.x + bi, p1.y + bi);
        *(float4*)(dst + 4) = make_float4(p2.x + bi, p2.y + bi, p3.x + bi, p3.y + bi);
    }
}

// ============================================================================
// Phase 3: persistent recurrence. 128 CTAs x 256 thr = 8 warps.
// warp = k-split (64 k), thread tile 8r x 4b; h slice loaded as 4 pipelined
// cp.async chunks overlapped with the FFMA2 k-loop.
// ============================================================================
#define P3_NCTA 128
#define WS_PAD 516
#define OFF_HS  (16 * WS_PAD * 4)            // 33024
#define OFF_ZSP (OFF_HS + 131072)            // 164096
#define OFF_ZXS (OFF_ZSP + 32768)            // 196864
#define SM_BYTES (OFF_ZXS + 8192)            // 205056

__global__ __launch_bounds__(256) void qlstm_recur(float* __restrict__ out, int out_size) {
    extern __shared__ unsigned char smraw[];
    float* Wsf = (float*)smraw;                     // [16][516] non-dup
    float* hs  = (float*)(smraw + OFF_HS);          // [512][64]
    float* zsp = (float*)(smraw + OFF_ZSP);         // [8 ks][16][64]
    float* zxs = (float*)(smraw + OFF_ZXS);         // [2][16][64]

    const int tid = threadIdx.x;
    const int bc  = blockIdx.x;
    const int c0  = bc * 4;

    // load weight slice (non-duplicated)
    #pragma unroll
    for (int u = 0; u < 32; u++) {
        int idx = tid + u * 256;
        int lr = idx >> 9, k = idx & 511;
        int gr = (lr >> 2) * 512 + c0 + (lr & 3);
        Wsf[lr * WS_PAD + k] = g_W[(size_t)gr * KTOT + 512 + k];
    }

    const int pf_lr = tid >> 4;
    const int pf_b  = (tid & 15) * 4;
    const int pf_gr = (pf_lr >> 2) * 512 + c0 + (pf_lr & 3);

    // prefetch zx[0]
    cp_async16(zxs + pf_lr * 64 + pf_b, g_zx + (size_t)pf_gr * BB + pf_b);
    CP_COMMIT();

    const int ep_j = tid >> 6, ep_b = tid & 63;
    g_h[0][(size_t)(c0 + ep_j) * BB + ep_b] = 0.0f;
    float creg = 0.0f, hlast = 0.0f;
    CP_WAIT(0);
    __threadfence();
    grid_barrier(P3_NCTA);

    const int ks    = tid >> 5;          // warp = k-split
    const int lane  = tid & 31;
    const int rgi   = (tid >> 4) & 1;    // row interleave bit
    const int b0    = (tid & 15) * 4;
    const int kbase = ks * 64;

    for (int s = 0; s < TT; s++) {
        const float* hsrc = g_h[s & 1];
        const float* src = hsrc + kbase * 64;
        float* dst = hs + kbase * 64;

        // issue zx[s+1] + 4 pipelined chunks of own 16KB h slice (4 groups)
        if (s + 1 < TT)
            cp_async16(zxs + ((s + 1) & 1) * 1024 + pf_lr * 64 + pf_b,
                       g_zx + ((size_t)(s + 1) * GG + pf_gr) * BB + pf_b);
        #pragma unroll
        for (int c = 0; c < 4; c++) {
            #pragma unroll
            for (int u = 0; u < 8; u++) {
                int idx = c * 256 + lane + u * 32;
                cp_async16(dst + idx * 4, src + idx * 4);
            }
            CP_COMMIT();
        }

        u64 acc[8][2];
        #pragma unroll
        for (int r = 0; r < 8; r++) { acc[r][0] = 0ULL; acc[r][1] = 0ULL; }

        const float* hbase = hs + kbase * 64 + b0;
        const float* wbase = Wsf + rgi * WS_PAD + kbase;

        // compute chunk-by-chunk as data lands
        #pragma unroll
        for (int c = 0; c < 4; c++) {
            if (c == 0)      { CP_WAIT(3); }
            else if (c == 1) { CP_WAIT(2); }
            else if (c == 2) { CP_WAIT(1); }
            else             { CP_WAIT(0); }
            __syncwarp();
            #pragma unroll
            for (int kb = c * 4; kb < c * 4 + 4; kb++) {
                ulonglong2 hq[4];
                #pragma unroll
                for (int j = 0; j < 4; j++)
                    hq[j] = *(const ulonglong2*)(hbase + (kb * 4 + j) * 64);
                #pragma unroll
                for (int rr = 0; rr < 8; rr++) {
                    float4 wv = *(const float4*)(wbase + rr * 2 * WS_PAD + kb * 4);
                    u64 w0 = pack2(wv.x, wv.x), w1 = pack2(wv.y, wv.y);
                    u64 w2 = pack2(wv.z, wv.z), w3 = pack2(wv.w, wv.w);
                    fma2(acc[rr][0], w0, hq[0].x); fma2(acc[rr][1], w0, hq[0].y);
                    fma2(acc[rr][0], w1, hq[1].x); fma2(acc[rr][1], w1, hq[1].y);
                    fma2(acc[rr][0], w2, hq[2].x); fma2(acc[rr][1], w2, hq[2].y);
                    fma2(acc[rr][0], w3, hq[3].x); fma2(acc[rr][1], w3, hq[3].y);
                }
            }
        }

        // write k-split partials
        #pragma unroll
        for (int rr = 0; rr < 8; rr++) {
            int lr = rr * 2 + rgi;
            float2 a = unpack2(acc[rr][0]);
            float2 c2 = unpack2(acc[rr][1]);
            *(float4*)&zsp[(ks * 16 + lr) * 64 + b0] = make_float4(a.x, a.y, c2.x, c2.y);
        }
        __syncthreads();

        // gate epilogue
        float z[4];
        #pragma unroll
        for (int gi = 0; gi < 4; gi++) {
            int row = gi * 4 + ep_j;
            float ssum = zxs[(s & 1) * 1024 + row * 64 + ep_b];
            #pragma unroll
            for (int q = 0; q < 8; q++)
                ssum += zsp[(q * 16 + row) * 64 + ep_b];
            z[gi] = ssum;
        }
        float fg = sigf(z[0]), ig = sigf(z[1]), ug = tanhf(z[2]), og = sigf(z[3]);
        creg = fg * creg + ig * ug;
        float hv = og * tanhf(creg);
        hlast = hv;
        g_h[(s + 1) & 1][(size_t)(c0 + ep_j) * BB + ep_b] = hv;
        out[((size_t)s * BB + ep_b) * HH + c0 + ep_j] = hv;

        grid_barrier(P3_NCTA);
    }

    size_t TBH = (size_t)TT * BB * HH;
    if ((size_t)out_size >= TBH + 2 * (size_t)BB * HH) {
        out[TBH + (size_t)ep_b * HH + c0 + ep_j] = hlast;
        out[TBH + (size_t)BB * HH + (size_t)ep_b * HH + c0 + ep_j] = creg;
    }
}

extern "C" void kernel_launch(void* const* d_in, const int* in_sizes, int n_in,
                              void* d_out, int out_size) {
    const float* X  = (const float*)d_in[0];
    const float* v  = (const float*)d_in[1];
    const float* g  = (const float*)d_in[2];
    const float* b  = (const float*)d_in[3];
    float* out = (float*)d_out;

    cudaFuncSetAttribute(qlstm_recur, cudaFuncAttributeMaxDynamicSharedMemorySize, SM_BYTES);

    qlstm_wnorm<<<GG, 256>>>(v, g);
    qlstm_gemm_x<<<dim3(GG / 128, TT / 2), 256>>>(X, b);
    qlstm_recur<<<P3_NCTA, 256, SM_BYTES>>>(out, out_size);
}